// round 5
// baseline (speedup 1.0000x reference)
#include <cuda_runtime.h>

#define BN 65536
#define DD 512
#define CC 50
#define NE (BN + CC)
#define FK 10
#define CPAD 56              // classes padded to 56
#define CH 28                // classes per chunk (2 chunks)
#define CF4 7                // float4 per chunk per k-row
#define CHP 14               // class pairs per chunk
#define HB 65536             // histogram bins
#define HSCALE 16384.0f      // bins per unit entropy (range [0,4))
#define CAP 4096             // candidate cap per rank (smem)

// ---------------- device state (no allocations allowed) ----------------
__device__ double g_sum_ent;
__device__ float  g_ent[NE];
__device__ float  g_conf[NE];
__device__ int    g_lab[NE];
__device__ unsigned char g_consist[BN];
__device__ float  g_scale[BN];                 // 20 / max(||feat_i||, 1e-12)
__device__ unsigned g_hist16[HB];
__device__ int    g_bucket[2];
__device__ int    g_rwith[2];
__device__ float  g_frac, g_thr, g_conf_thr;
__device__ __align__(16) float g_centT[DD * CPAD];   // transposed padded centroids

// ---------------- helpers ----------------
__device__ __forceinline__ void ffma2(unsigned long long &d,
                                      unsigned long long a,
                                      unsigned long long b) {
    asm("fma.rn.f32x2 %0, %1, %2, %0;" : "+l"(d) : "l"(a), "l"(b));
}
__device__ __forceinline__ unsigned long long splat2(float f) {
    unsigned long long r;
    asm("mov.b64 %0, {%1,%1};" : "=l"(r) : "f"(f));
    return r;
}
__device__ __forceinline__ unsigned long long pack2(float x, float y) {
    unsigned long long r;
    asm("mov.b64 %0, {%1,%2};" : "=l"(r) : "f"(x), "f"(y));
    return r;
}
__device__ __forceinline__ void unpack2(unsigned long long v, float &lo, float &hi) {
    asm("mov.b64 {%0,%1}, %2;" : "=f"(lo), "=f"(hi) : "l"(v));
}
__device__ __forceinline__ unsigned fkey(float f) {
    unsigned u = __float_as_uint(f);
    return (u & 0x80000000u) ? ~u : (u | 0x80000000u);
}
__device__ __forceinline__ int ent_bucket(float e) {
    int b = (int)(e * HSCALE);
    return min(max(b, 0), HB - 1);
}

// ---- shared GEMM chunk: 2 rows/thread x 28 classes, FFMA2, K=512 ----
template<bool NRM>
__device__ __forceinline__ void gemm_chunk(
    const float4* __restrict__ f0p, const float4* __restrict__ f1p,
    const float* __restrict__ sbase,
    unsigned long long* acc0, unsigned long long* acc1,
    float& nrm0, float& nrm1)
{
    float4 cur0 = f0p[0], cur1 = f1p[0];
    float4 nx0  = f0p[1], nx1  = f1p[1];
#pragma unroll 1
    for (int it = 0; it < DD / 4; ++it) {
        int ip = min(it + 2, DD / 4 - 1);
        float4 pf0 = f0p[ip], pf1 = f1p[ip];
        float a0v[4] = {cur0.x, cur0.y, cur0.z, cur0.w};
        float a1v[4] = {cur1.x, cur1.y, cur1.z, cur1.w};
#pragma unroll
        for (int kk = 0; kk < 4; kk++) {
            unsigned long long s0 = splat2(a0v[kk]);
            unsigned long long s1 = splat2(a1v[kk]);
            if (NRM) {
                nrm0 = fmaf(a0v[kk], a0v[kk], nrm0);
                nrm1 = fmaf(a1v[kk], a1v[kk], nrm1);
            }
            const float4* wr = (const float4*)(sbase + (it * 4 + kk) * CPAD);
#pragma unroll
            for (int j = 0; j < CF4; j++) {
                float4 w = wr[j];
                unsigned long long wlo = pack2(w.x, w.y);
                unsigned long long whi = pack2(w.z, w.w);
                ffma2(acc0[2 * j],     s0, wlo);
                ffma2(acc0[2 * j + 1], s0, whi);
                ffma2(acc1[2 * j],     s1, wlo);
                ffma2(acc1[2 * j + 1], s1, whi);
            }
        }
        cur0 = nx0; cur1 = nx1;
        nx0 = pf0;  nx1 = pf1;
    }
}

// ---------------- 1) warmup memory stats: wl = W@W.T + b ----------------
__global__ void k_warmup(const float* __restrict__ W, const float* __restrict__ b) {
    int c1 = blockIdx.x, tid = threadIdx.x;  // 50 blocks x 64 threads
    __shared__ float sw[DD];
    __shared__ float sl[CC];
    for (int k = tid; k < DD; k += 64) sw[k] = W[(size_t)c1 * DD + k];
    __syncthreads();
    if (tid < CC) {
        const float* wj = W + (size_t)tid * DD;
        float acc = 0.f;
        for (int k = 0; k < DD; k++) acc += sw[k] * wj[k];
        sl[tid] = acc + b[tid];
    }
    __syncthreads();
    if (tid == 0) {
        float mx = sl[0]; int arg = 0;
        for (int c = 1; c < CC; c++) if (sl[c] > mx) { mx = sl[c]; arg = c; }
        float se = 0.f, sw2 = 0.f;
        for (int c = 0; c < CC; c++) {
            float e = __expf(sl[c] - mx);
            se += e; sw2 += e * sl[c];
        }
        float lse = mx + __logf(se);
        g_ent[c1]  = lse - sw2 / se;
        g_conf[c1] = 1.0f / se;
        g_lab[c1]  = arg;
    }
    // per-replay state reset: histogram + running sum
    for (int i = blockIdx.x * 64 + tid; i < HB; i += CC * 64) g_hist16[i] = 0u;
    if (c1 == 0 && tid == 0) g_sum_ent = 0.0;
}

// ---------------- 2) main GEMM + per-row stats (class-chunked) ------------
__global__ __launch_bounds__(256, 1)
void k_main(const float* __restrict__ feat, const float* __restrict__ lraw,
            const float* __restrict__ laug, const float* __restrict__ W,
            const float* __restrict__ b) {
    extern __shared__ float sWt[];                // [DD][CPAD] transposed W
    __shared__ float sB[CPAD];
    __shared__ double red[256];
    int tid = threadIdx.x;

    for (int idx = tid; idx < CC * DD; idx += 256) {
        int c = idx >> 9, k = idx & 511;
        sWt[k * CPAD + c] = W[idx];
    }
    for (int k = tid; k < DD; k += 256)
#pragma unroll
        for (int p = CC; p < CPAD; p++) sWt[k * CPAD + p] = 0.f;
    if (tid < CPAD) sB[tid] = (tid < CC) ? b[tid] : 0.f;
    __syncthreads();

    int row0 = blockIdx.x * 512 + tid;
    int row1 = row0 + 256;
    const float4* f0p = (const float4*)(feat + (size_t)row0 * DD);
    const float4* f1p = (const float4*)(feat + (size_t)row1 * DD);

    float lg0[CPAD], lg1[CPAD];
    float nrm0 = 0.f, nrm1 = 0.f;

    {   // chunk 0: classes [0,28)
        unsigned long long acc0[CHP], acc1[CHP];
#pragma unroll
        for (int j = 0; j < CHP; j++) { acc0[j] = 0ull; acc1[j] = 0ull; }
        gemm_chunk<true>(f0p, f1p, sWt, acc0, acc1, nrm0, nrm1);
#pragma unroll
        for (int j = 0; j < CHP; j++) {
            unpack2(acc0[j], lg0[2 * j], lg0[2 * j + 1]);
            unpack2(acc1[j], lg1[2 * j], lg1[2 * j + 1]);
        }
    }
    {   // chunk 1: classes [28,56)
        unsigned long long acc0[CHP], acc1[CHP];
#pragma unroll
        for (int j = 0; j < CHP; j++) { acc0[j] = 0ull; acc1[j] = 0ull; }
        gemm_chunk<false>(f0p, f1p, sWt + CH, acc0, acc1, nrm0, nrm1);
#pragma unroll
        for (int j = 0; j < CHP; j++) {
            unpack2(acc0[j], lg0[CH + 2 * j], lg0[CH + 2 * j + 1]);
            unpack2(acc1[j], lg1[CH + 2 * j], lg1[CH + 2 * j + 1]);
        }
    }

    float entv[2];
#pragma unroll
    for (int rr = 0; rr < 2; rr++) {
        int row = rr ? row1 : row0;
        float nrm = rr ? nrm1 : nrm0;
        float lg[CC];
#pragma unroll
        for (int c = 0; c < CC; c++) lg[c] = (rr ? lg1[c] : lg0[c]) + sB[c];
        float mx = lg[0]; int arg = 0;
#pragma unroll
        for (int c = 1; c < CC; c++) if (lg[c] > mx) { mx = lg[c]; arg = c; }
        float se = 0.f, sl = 0.f;
#pragma unroll
        for (int c = 0; c < CC; c++) {
            float e = __expf(lg[c] - mx);
            se += e; sl += e * lg[c];
        }
        float lse  = mx + __logf(se);
        float ent  = lse - sl / se;
        float pmax = 1.0f / se;
        float inv  = 1.0f / fmaxf(sqrtf(nrm), 1e-12f);

        const float2* r2 = (const float2*)(lraw + (size_t)row * CC);
        const float2* a2 = (const float2*)(laug + (size_t)row * CC);
        float b1 = -3.4e38f, b2 = -3.4e38f; int i1 = 0, i2 = 0;
#pragma unroll
        for (int j = 0; j < CC / 2; j++) {
            float2 v = r2[j];
            if (v.x > b1) { b1 = v.x; i1 = 2 * j; }
            if (v.y > b1) { b1 = v.y; i1 = 2 * j + 1; }
            float2 u = a2[j];
            if (u.x > b2) { b2 = u.x; i2 = 2 * j; }
            if (u.y > b2) { b2 = u.y; i2 = 2 * j + 1; }
        }

        g_consist[row]   = (unsigned char)(i1 == i2);
        g_ent[CC + row]  = ent;
        g_conf[CC + row] = pmax;
        g_lab[CC + row]  = arg;
        g_scale[row]     = 20.0f * inv;
        atomicAdd(&g_hist16[ent_bucket(ent)], 1u);
        entv[rr] = ent;
    }

    red[tid] = (double)entv[0] + (double)entv[1];
    __syncthreads();
    for (int s = 128; s; s >>= 1) {
        if (tid < s) red[tid] += red[tid + s];
        __syncthreads();
    }
    if (tid == 0) atomicAdd(&g_sum_ent, red[0]);
}

// -------- 3) fused branch + histogram scan (1 block, 1024 threads) --------
__global__ void k_branchscan() {
    __shared__ unsigned sc[1024];
    __shared__ int s_rank[2];
    int tid = threadIdx.x;
    if (tid == 0) {
        float m = (float)(g_sum_ent / (double)BN);
        float q = (m >= 0.45f) ? 0.25f : ((m >= 0.38f) ? 0.3f : 0.4f);
        g_conf_thr = (m >= 0.45f) ? 0.72f : 0.62f;
        float pos = q * (float)(BN - 1);
        float lof = floorf(pos);
        g_frac = pos - lof;
        s_rank[0] = (int)lof;
        s_rank[1] = min((int)lof + 1, BN - 1);
    }
    __syncthreads();
    int base = tid * (HB / 1024);
    unsigned local = 0;
    for (int j = 0; j < HB / 1024; j++) local += g_hist16[base + j];
    sc[tid] = local;
    __syncthreads();
    for (int off = 1; off < 1024; off <<= 1) {
        unsigned v = 0;
        if (tid >= off) v = sc[tid - off];
        __syncthreads();
        if (tid >= off) sc[tid] += v;
        __syncthreads();
    }
    unsigned incl = sc[tid];
    unsigned before = incl - local;
    for (int s = 0; s < 2; s++) {
        unsigned r = (unsigned)s_rank[s];
        if (before <= r && r < incl) {
            unsigned acc = before;
            for (int j = 0; j < HB / 1024; j++) {
                unsigned c = g_hist16[base + j];
                if (r < acc + c) {
                    g_bucket[s] = base + j;
                    g_rwith[s]  = (int)(r - acc);
                    break;
                }
                acc += c;
            }
        }
    }
}

// -------- 4) fused candidate gather + exact rank pick (1 block) -----------
__global__ void k_selectpick() {
    __shared__ float cand[2][CAP];
    __shared__ int   cn[2];
    __shared__ float qv[2];
    int tid = threadIdx.x;                       // 1024 threads
    if (tid < 2) cn[tid] = 0;
    __syncthreads();
    int b0 = g_bucket[0], b1 = g_bucket[1];
    for (int i = tid; i < BN; i += 1024) {
        float e = g_ent[CC + i];
        int bb = ent_bucket(e);
        if (bb == b0) {
            int p = atomicAdd(&cn[0], 1);
            if (p < CAP) cand[0][p] = e;
        }
        if (bb == b1) {
            int p = atomicAdd(&cn[1], 1);
            if (p < CAP) cand[1][p] = e;
        }
    }
    __syncthreads();
    for (int s = 0; s < 2; s++) {
        int n = min(cn[s], CAP);
        int r = g_rwith[s];
        for (int i = tid; i < n; i += 1024) {
            float v = cand[s][i];
            int rank = 0;
            for (int j = 0; j < n; j++) {
                float u = cand[s][j];
                rank += (u < v) || (u == v && j < i);
            }
            if (rank == r) qv[s] = v;
        }
        __syncthreads();
    }
    if (tid == 0) {
        float f = g_frac;
        g_thr = qv[0] * (1.0f - f) + qv[1] * f;
    }
}

// -------- 5) fused per-class top-10 (inline validity) + centroid ----------
__global__ void k_topkcent(const float* __restrict__ feat,
                           const float* __restrict__ W) {
    int c = blockIdx.x, tid = threadIdx.x;       // 50 blocks x 256
    float thr = g_thr, cthr = g_conf_thr;

    unsigned long long loc[FK];
#pragma unroll
    for (int j = 0; j < FK; j++) loc[j] = ~0ull;

    for (int e = tid; e < NE; e += 256) {
        if (g_lab[e] != c) continue;
        bool valid = (e < CC) ||
                     ((g_ent[e] <= thr) && g_consist[e - CC] && (g_conf[e] >= cthr));
        if (!valid) continue;
        unsigned long long k =
            (((unsigned long long)fkey(g_ent[e])) << 32) | (unsigned)e;
        if (k < loc[FK - 1]) {
            loc[FK - 1] = k;
#pragma unroll
            for (int j = FK - 1; j > 0; j--) {
                if (loc[j] < loc[j - 1]) {
                    unsigned long long t = loc[j];
                    loc[j] = loc[j - 1];
                    loc[j - 1] = t;
                }
            }
        }
    }

    __shared__ unsigned long long sh[256];
    __shared__ int   s_idx[FK];
    __shared__ float s_w[FK];
    int ptr = 0;
    for (int j = 0; j < FK; j++) {
        sh[tid] = (ptr < FK) ? loc[ptr] : ~0ull;
        __syncthreads();
        for (int s = 128; s; s >>= 1) {
            if (tid < s) {
                unsigned long long x = sh[tid], y = sh[tid + s];
                sh[tid] = (y < x) ? y : x;
            }
            __syncthreads();
        }
        unsigned long long win = sh[0];
        __syncthreads();
        if (ptr < FK && loc[ptr] == win && win != ~0ull) ptr++;
        if (tid == 0) {
            if (win != ~0ull) {
                int idx = (int)(win & 0xffffffffu);
                s_idx[j] = idx;
                s_w[j]   = fmaxf(g_conf[idx], 1e-6f);
            } else {
                s_idx[j] = -1;
            }
        }
        __syncthreads();
    }

    // ---- centroid for class c ----
    __shared__ float red[256];
    float a0 = 0.f, a1 = 0.f;
    for (int j = 0; j < FK; j++) {
        int idx = s_idx[j];                       // uniform across block
        if (idx >= 0) {
            const float* v = (idx < CC) ? (W + (size_t)idx * DD)
                                        : (feat + (size_t)(idx - CC) * DD);
            float x0 = v[tid], x1 = v[tid + 256];
            red[tid] = x0 * x0 + x1 * x1;
            __syncthreads();
            for (int s = 128; s; s >>= 1) {
                if (tid < s) red[tid] += red[tid + s];
                __syncthreads();
            }
            float w = s_w[j] / fmaxf(sqrtf(red[0]), 1e-12f);
            __syncthreads();
            a0 += w * x0;
            a1 += w * x1;
        }
    }
    red[tid] = a0 * a0 + a1 * a1;
    __syncthreads();
    for (int s = 128; s; s >>= 1) {
        if (tid < s) red[tid] += red[tid + s];
        __syncthreads();
    }
    float n = fmaxf(sqrtf(red[0]), 1e-12f);
    g_centT[(size_t)tid * CPAD + c]         = a0 / n;
    g_centT[(size_t)(tid + 256) * CPAD + c] = a1 / n;
    if (c == 0) {                                // zero pad columns
        for (int k = tid; k < DD; k += 256)
#pragma unroll
            for (int p = CC; p < CPAD; p++) g_centT[(size_t)k * CPAD + p] = 0.f;
    }
}

// ---------------- 6) output GEMM: 20 * normalize(feat) @ centroids.T ------
__global__ __launch_bounds__(256, 1)
void k_out(const float* __restrict__ feat, float* __restrict__ out) {
    extern __shared__ float sC[];                 // [DD][CPAD]
    int tid = threadIdx.x;
    for (int i = tid; i < DD * CPAD / 4; i += 256)
        ((float4*)sC)[i] = ((const float4*)g_centT)[i];
    __syncthreads();

    int row0 = blockIdx.x * 512 + tid;
    int row1 = row0 + 256;
    const float4* f0p = (const float4*)(feat + (size_t)row0 * DD);
    const float4* f1p = (const float4*)(feat + (size_t)row1 * DD);

    float lg0[CPAD], lg1[CPAD];
    float dum0 = 0.f, dum1 = 0.f;

    {
        unsigned long long acc0[CHP], acc1[CHP];
#pragma unroll
        for (int j = 0; j < CHP; j++) { acc0[j] = 0ull; acc1[j] = 0ull; }
        gemm_chunk<false>(f0p, f1p, sC, acc0, acc1, dum0, dum1);
#pragma unroll
        for (int j = 0; j < CHP; j++) {
            unpack2(acc0[j], lg0[2 * j], lg0[2 * j + 1]);
            unpack2(acc1[j], lg1[2 * j], lg1[2 * j + 1]);
        }
    }
    {
        unsigned long long acc0[CHP], acc1[CHP];
#pragma unroll
        for (int j = 0; j < CHP; j++) { acc0[j] = 0ull; acc1[j] = 0ull; }
        gemm_chunk<false>(f0p, f1p, sC + CH, acc0, acc1, dum0, dum1);
#pragma unroll
        for (int j = 0; j < CHP; j++) {
            unpack2(acc0[j], lg0[CH + 2 * j], lg0[CH + 2 * j + 1]);
            unpack2(acc1[j], lg1[CH + 2 * j], lg1[CH + 2 * j + 1]);
        }
    }

#pragma unroll
    for (int rr = 0; rr < 2; rr++) {
        int row = rr ? row1 : row0;
        float s = g_scale[row];
        float2* o2 = (float2*)(out + (size_t)row * CC);
#pragma unroll
        for (int j = 0; j < CC / 2; j++) {
            float2 v;
            v.x = s * (rr ? lg1[2 * j]     : lg0[2 * j]);
            v.y = s * (rr ? lg1[2 * j + 1] : lg0[2 * j + 1]);
            o2[j] = v;
        }
    }
}

// ---------------- host ----------------
extern "C" void kernel_launch(void* const* d_in, const int* in_sizes, int n_in,
                              void* d_out, int out_size) {
    const float* feat = (const float*)d_in[0];
    const float* lraw = (const float*)d_in[1];
    const float* laug = (const float*)d_in[2];
    const float* W    = (const float*)d_in[3];
    const float* b    = (const float*)d_in[4];
    float* out = (float*)d_out;

    size_t shmem = (size_t)DD * CPAD * sizeof(float);   // 114,688 B
    cudaFuncSetAttribute(k_main, cudaFuncAttributeMaxDynamicSharedMemorySize, (int)shmem);
    cudaFuncSetAttribute(k_out,  cudaFuncAttributeMaxDynamicSharedMemorySize, (int)shmem);

    k_warmup<<<CC, 64>>>(W, b);                 // launch 1
    k_main<<<BN / 512, 256, shmem>>>(feat, lraw, laug, W, b);  // 2
    k_branchscan<<<1, 1024>>>();                // 3
    k_selectpick<<<1, 1024>>>();                // 4
    k_topkcent<<<CC, 256>>>(feat, W);           // 5
    k_out<<<BN / 512, 256, shmem>>>(feat, out); // 6  <- ncu window (-s 5 -c 1)
}